// round 14
// baseline (speedup 1.0000x reference)
#include <cuda_runtime.h>

// All-pairs N-body gravity — single graph node, conflict-free edition.
// R13 diagnosis: slice stride in shared was 128B = exact bank wrap, so the
// 4 slices resident in each warp made every LDS.64 a 4-way bank conflict
// (L1=37%, +10us). Fix: pad slice stride to CW+1 words (136B -> 2-bank
// offset per slice; warp's 4 slice-groups hit disjoint bank pairs ->
// conflict-free multi-broadcast). CHUNK 32->64 halves barriers. Inner loop
// is R5's proven packed-f32x2 IPT=2. One plain STG per output element,
// no atomics, no zero pass (single-node gap measured at 1.5us vs 3.3us).

#define BLOCK   256
#define ITILE   16                 // i per CTA
#define NSLICE  32                 // j-slices
#define JSLICE  256                // j per slice (8192/32)
#define CHUNK   64                 // j per slice per staging round
#define CW      (CHUNK / 2)        // packed words per slice per round = 32
#define SSW     (CW + 1)           // padded slice stride in u64 words
#define NROUND  (JSLICE / CHUNK)   // 4
#define EPS2    0.0001f            // SOFTENING^2

typedef unsigned long long u64;

__device__ __forceinline__ u64 pack2(float lo, float hi) {
    u64 r;
    asm("mov.b64 %0, {%1, %2};" : "=l"(r)
        : "r"(__float_as_uint(lo)), "r"(__float_as_uint(hi)));
    return r;
}
__device__ __forceinline__ void unpack2(u64 v, float& lo, float& hi) {
    unsigned a, b;
    asm("mov.b64 {%0, %1}, %2;" : "=r"(a), "=r"(b) : "l"(v));
    lo = __uint_as_float(a);
    hi = __uint_as_float(b);
}
__device__ __forceinline__ u64 f2add(u64 a, u64 b) {
    u64 r; asm("add.rn.f32x2 %0, %1, %2;" : "=l"(r) : "l"(a), "l"(b)); return r;
}
__device__ __forceinline__ u64 f2mul(u64 a, u64 b) {
    u64 r; asm("mul.rn.f32x2 %0, %1, %2;" : "=l"(r) : "l"(a), "l"(b)); return r;
}
__device__ __forceinline__ u64 f2fma(u64 a, u64 b, u64 c) {
    u64 r; asm("fma.rn.f32x2 %0, %1, %2, %3;"
               : "=l"(r) : "l"(a), "l"(b), "l"(c)); return r;
}
__device__ __forceinline__ float rsq_mufu(float x) {
    float r; asm("rsqrt.approx.f32 %0, %1;" : "=f"(r) : "f"(x)); return r;
}

__global__ __launch_bounds__(BLOCK)
void nbody_forces_kernel(const float* __restrict__ pos,
                         const float* __restrict__ mass,
                         float* __restrict__ out) {
    // Packed SoA staging, padded slice stride (conflict-free multi-broadcast).
    __shared__ u64 sx[NSLICE * SSW], sy[NSLICE * SSW],
                   sz[NSLICE * SSW], sm[NSLICE * SSW];
    __shared__ float red[NSLICE][3][ITILE + 1];

    const int tid   = threadIdx.x;
    const int slice = tid >> 3;        // 0..31 (warp holds 4 adjacent slices)
    const int ig    = tid & 7;         // i-group 0..7
    const int i0    = blockIdx.x * ITILE + ig;
    const int i1    = i0 + 8;

    const u64 nx0 = pack2(-pos[3 * i0 + 0], -pos[3 * i0 + 0]);
    const u64 ny0 = pack2(-pos[3 * i0 + 1], -pos[3 * i0 + 1]);
    const u64 nz0 = pack2(-pos[3 * i0 + 2], -pos[3 * i0 + 2]);
    const u64 nx1 = pack2(-pos[3 * i1 + 0], -pos[3 * i1 + 0]);
    const u64 ny1 = pack2(-pos[3 * i1 + 1], -pos[3 * i1 + 1]);
    const u64 nz1 = pack2(-pos[3 * i1 + 2], -pos[3 * i1 + 2]);
    const u64 eps22 = pack2(EPS2, EPS2);

    u64 ax0 = 0ull, ay0 = 0ull, az0 = 0ull;
    u64 ax1 = 0ull, ay1 = 0ull, az1 = 0ull;

    for (int r = 0; r < NROUND; ++r) {
        __syncthreads();
        // Stage 64 j for each of 32 slices (2048 j; 8 elems/thread).
#pragma unroll
        for (int idx = tid; idx < NSLICE * CHUNK; idx += BLOCK) {
            const int s = idx >> 6;                  // slice
            const int q = idx & 63;                  // j within chunk
            const int j = s * JSLICE + r * CHUNK + q;
            const int f = s * (2 * SSW) + q;         // padded float index
            ((float*)sx)[f] = pos[3 * j + 0];
            ((float*)sy)[f] = pos[3 * j + 1];
            ((float*)sz)[f] = pos[3 * j + 2];
            ((float*)sm)[f] = mass[j];
        }
        __syncthreads();

        const int base = slice * SSW;
#pragma unroll 4
        for (int t = 0; t < CW; ++t) {
            const u64 px = sx[base + t];   // conflict-free multi-broadcast
            const u64 py = sy[base + t];
            const u64 pz = sz[base + t];
            const u64 pm = sm[base + t];

            // chain 0
            u64 dx0 = f2add(px, nx0);
            u64 dy0 = f2add(py, ny0);
            u64 dz0 = f2add(pz, nz0);
            // chain 1 (independent)
            u64 dx1 = f2add(px, nx1);
            u64 dy1 = f2add(py, ny1);
            u64 dz1 = f2add(pz, nz1);

            u64 r20 = f2fma(dx0, dx0, f2fma(dy0, dy0, f2fma(dz0, dz0, eps22)));
            u64 r21 = f2fma(dx1, dx1, f2fma(dy1, dy1, f2fma(dz1, dz1, eps22)));

            float a, b;
            unpack2(r20, a, b);
            u64 inv0 = pack2(rsq_mufu(a), rsq_mufu(b));
            unpack2(r21, a, b);
            u64 inv1 = pack2(rsq_mufu(a), rsq_mufu(b));

            u64 s0 = f2mul(pm, f2mul(f2mul(inv0, inv0), inv0));
            u64 s1 = f2mul(pm, f2mul(f2mul(inv1, inv1), inv1));

            ax0 = f2fma(s0, dx0, ax0);
            ay0 = f2fma(s0, dy0, ay0);
            az0 = f2fma(s0, dz0, az0);
            ax1 = f2fma(s1, dx1, ax1);
            ay1 = f2fma(s1, dy1, ay1);
            az1 = f2fma(s1, dz1, az1);
        }
    }

    float l, h;
    unpack2(ax0, l, h); red[slice][0][ig]     = l + h;
    unpack2(ay0, l, h); red[slice][1][ig]     = l + h;
    unpack2(az0, l, h); red[slice][2][ig]     = l + h;
    unpack2(ax1, l, h); red[slice][0][ig + 8] = l + h;
    unpack2(ay1, l, h); red[slice][1][ig + 8] = l + h;
    unpack2(az1, l, h); red[slice][2][ig + 8] = l + h;
    __syncthreads();

    if (tid < ITILE * 3) {
        const int ii  = tid & 15;
        const int dim = tid >> 4;          // 0..2
        float v = 0.0f;
#pragma unroll
        for (int s = 0; s < NSLICE; ++s) v += red[s][dim][ii];
        out[3 * (blockIdx.x * ITILE + ii) + dim] = v;   // one plain store
    }
}

extern "C" void kernel_launch(void* const* d_in, const int* in_sizes, int n_in,
                              void* d_out, int out_size) {
    const float* pos  = (const float*)d_in[0];   // [N,3] float32
    const float* mass = (const float*)d_in[1];   // [N]   float32
    float* out = (float*)d_out;                  // [N,3] float32

    const int n = in_sizes[0] / 3;               // 8192

    nbody_forces_kernel<<<n / ITILE, BLOCK>>>(pos, mass, out);   // 512 CTAs
}

// round 15
// speedup vs baseline: 1.1938x; 1.1938x over previous
#include <cuda_runtime.h>

// All-pairs N-body gravity — R5/R11's proven 36.0us kernel made SINGLE-node.
// Measured: two-node replay gap 3.3us, single-node 1.5us -> the aux node
// costs ~1.8us. R12-R14 showed restructuring the j-loop into one CTA costs
// +12us, so instead keep the 2-D grid + atomics but accumulate into a
// persistent __device__ scratch (static-zero). Last-arriving j-block CTA per
// i-block (arrival counter) copies scratch->out with plain stores and resets
// scratch+counter to zero, restoring the invariant for the next replay.

#define BLOCK  256
#define IPT    2
#define JCHUNK 64
#define JP     (JCHUNK / 2)
#define NJB    128              // j-blocks = 8192 / JCHUNK
#define NIB    16               // i-blocks = 8192 / (BLOCK*IPT)
#define EPS2   0.0001f          // SOFTENING^2

typedef unsigned long long u64;

__device__ float        g_scratch[8192 * 3];   // zero-initialized at load
__device__ unsigned int g_count[NIB];          // zero-initialized at load

__device__ __forceinline__ u64 pack2(float lo, float hi) {
    u64 r;
    asm("mov.b64 %0, {%1, %2};" : "=l"(r)
        : "r"(__float_as_uint(lo)), "r"(__float_as_uint(hi)));
    return r;
}
__device__ __forceinline__ void unpack2(u64 v, float& lo, float& hi) {
    unsigned a, b;
    asm("mov.b64 {%0, %1}, %2;" : "=r"(a), "=r"(b) : "l"(v));
    lo = __uint_as_float(a);
    hi = __uint_as_float(b);
}
__device__ __forceinline__ u64 f2add(u64 a, u64 b) {
    u64 r; asm("add.rn.f32x2 %0, %1, %2;" : "=l"(r) : "l"(a), "l"(b)); return r;
}
__device__ __forceinline__ u64 f2mul(u64 a, u64 b) {
    u64 r; asm("mul.rn.f32x2 %0, %1, %2;" : "=l"(r) : "l"(a), "l"(b)); return r;
}
__device__ __forceinline__ u64 f2fma(u64 a, u64 b, u64 c) {
    u64 r; asm("fma.rn.f32x2 %0, %1, %2, %3;"
               : "=l"(r) : "l"(a), "l"(b), "l"(c)); return r;
}
__device__ __forceinline__ float rsq_mufu(float x) {
    float r; asm("rsqrt.approx.f32 %0, %1;" : "=f"(r) : "f"(x)); return r;
}

__global__ __launch_bounds__(BLOCK)
void nbody_forces_kernel(const float* __restrict__ pos,
                         const float* __restrict__ mass,
                         float* __restrict__ out) {
    __shared__ u64 sx[JP], sy[JP], sz[JP], sm[JP];
    __shared__ int s_last;

    const int tid   = threadIdx.x;
    const int i0    = blockIdx.x * (BLOCK * IPT) + tid;
    const int i1    = i0 + BLOCK;
    const int jbase = blockIdx.y * JCHUNK;

    if (tid < JCHUNK) {
        int j = jbase + tid;
        ((float*)sx)[tid] = pos[3 * j + 0];
        ((float*)sy)[tid] = pos[3 * j + 1];
        ((float*)sz)[tid] = pos[3 * j + 2];
        ((float*)sm)[tid] = mass[j];
    }
    __syncthreads();

    const u64 nx0 = pack2(-pos[3 * i0 + 0], -pos[3 * i0 + 0]);
    const u64 ny0 = pack2(-pos[3 * i0 + 1], -pos[3 * i0 + 1]);
    const u64 nz0 = pack2(-pos[3 * i0 + 2], -pos[3 * i0 + 2]);
    const u64 nx1 = pack2(-pos[3 * i1 + 0], -pos[3 * i1 + 0]);
    const u64 ny1 = pack2(-pos[3 * i1 + 1], -pos[3 * i1 + 1]);
    const u64 nz1 = pack2(-pos[3 * i1 + 2], -pos[3 * i1 + 2]);
    const u64 eps22 = pack2(EPS2, EPS2);

    u64 ax0 = 0ull, ay0 = 0ull, az0 = 0ull;
    u64 ax1 = 0ull, ay1 = 0ull, az1 = 0ull;

#pragma unroll 4
    for (int t = 0; t < JP; ++t) {
        const u64 px = sx[t];              // LDS.64 broadcast feeds 4 pairs
        const u64 py = sy[t];
        const u64 pz = sz[t];
        const u64 pm = sm[t];

        u64 dx0 = f2add(px, nx0);
        u64 dy0 = f2add(py, ny0);
        u64 dz0 = f2add(pz, nz0);
        u64 dx1 = f2add(px, nx1);
        u64 dy1 = f2add(py, ny1);
        u64 dz1 = f2add(pz, nz1);

        u64 r20 = f2fma(dx0, dx0, f2fma(dy0, dy0, f2fma(dz0, dz0, eps22)));
        u64 r21 = f2fma(dx1, dx1, f2fma(dy1, dy1, f2fma(dz1, dz1, eps22)));

        float a, b;
        unpack2(r20, a, b);
        u64 inv0 = pack2(rsq_mufu(a), rsq_mufu(b));
        unpack2(r21, a, b);
        u64 inv1 = pack2(rsq_mufu(a), rsq_mufu(b));

        u64 s0 = f2mul(pm, f2mul(f2mul(inv0, inv0), inv0));
        u64 s1 = f2mul(pm, f2mul(f2mul(inv1, inv1), inv1));

        ax0 = f2fma(s0, dx0, ax0);
        ay0 = f2fma(s0, dy0, ay0);
        az0 = f2fma(s0, dz0, az0);
        ax1 = f2fma(s1, dx1, ax1);
        ay1 = f2fma(s1, dy1, ay1);
        az1 = f2fma(s1, dz1, az1);
    }

    // Accumulate partials into persistent scratch (zero by invariant).
    float l, h;
    unpack2(ax0, l, h); atomicAdd(&g_scratch[3 * i0 + 0], l + h);
    unpack2(ay0, l, h); atomicAdd(&g_scratch[3 * i0 + 1], l + h);
    unpack2(az0, l, h); atomicAdd(&g_scratch[3 * i0 + 2], l + h);
    unpack2(ax1, l, h); atomicAdd(&g_scratch[3 * i1 + 0], l + h);
    unpack2(ay1, l, h); atomicAdd(&g_scratch[3 * i1 + 1], l + h);
    unpack2(az1, l, h); atomicAdd(&g_scratch[3 * i1 + 2], l + h);

    // Arrival protocol: last j-block CTA for this i-block finalizes.
    __threadfence();
    __syncthreads();
    if (tid == 0) {
        unsigned prev = atomicAdd(&g_count[blockIdx.x], 1u);
        s_last = (prev == NJB - 1u);
    }
    __syncthreads();

    if (s_last) {
        __threadfence();   // acquire: all scratch atomics now visible
        const int base = blockIdx.x * (BLOCK * IPT) * 3;   // 1536 floats
#pragma unroll
        for (int q = 0; q < 6; ++q) {
            const int idx = base + q * BLOCK + tid;
            out[idx] = g_scratch[idx];     // plain store (out was poisoned)
            g_scratch[idx] = 0.0f;         // restore invariant for next replay
        }
        if (tid == 0) g_count[blockIdx.x] = 0u;
    }
}

extern "C" void kernel_launch(void* const* d_in, const int* in_sizes, int n_in,
                              void* d_out, int out_size) {
    const float* pos  = (const float*)d_in[0];   // [N,3] float32
    const float* mass = (const float*)d_in[1];   // [N]   float32
    float* out = (float*)d_out;                  // [N,3] float32

    const int n = in_sizes[0] / 3;               // 8192

    dim3 grid(n / (BLOCK * IPT), n / JCHUNK);    // 16 x 128 = 2048 CTAs
    nbody_forces_kernel<<<grid, BLOCK>>>(pos, mass, out);   // single node
}